// round 1
// baseline (speedup 1.0000x reference)
#include <cuda_runtime.h>
#include <cstdint>

#define EPSBN 0.001f

// ---------------- static device scratch (no allocations allowed) ----------------
__device__ float g_bufA[32u * 262144u];   // 33.5 MB ping
__device__ float g_bufB[32u * 262144u];   // 33.5 MB pong
__device__ float g_m0[262144];            // mask at 64^3
__device__ float g_m1[32768];             // mask at 32^3
__device__ float g_m2[4096];              // mask at 16^3
__device__ float g_pxy[16 * 16 * 128];    // planes, layout [(a*16+b)*128 + c]
__device__ float g_pyz[16 * 16 * 128];
__device__ float g_pxz[16 * 16 * 128];
__device__ float g_scale[1024];
__device__ float g_shift[1024];
__device__ int   g_flags[2];

// ---------------- mask dtype detection + expansion ----------------
__global__ void k_init_flags() {
    if (threadIdx.x < 2) g_flags[threadIdx.x] = 0;
}

// Read the mask buffer as 32-bit words (65536 words is safe for all candidate
// dtypes: uint8 -> 262144 B exactly; int32/float32 -> 1 MB).
// int32 0/1 data  : every word in {0,1}
// float 0.0/1.0   : every word in {0, 0x3F800000}
// uint8 0/1 bytes : words mix bytes -> neither property holds
__global__ void k_detect(const unsigned int* __restrict__ m) {
    int i = blockIdx.x * blockDim.x + threadIdx.x;
    if (i < 65536) {
        unsigned v = m[i];
        if (v != 0u && v != 0x3F800000u) atomicOr(&g_flags[0], 1);
        if (v > 1u) atomicOr(&g_flags[1], 1);
    }
}

__global__ void k_expand_mask(const void* __restrict__ mp, float* __restrict__ o) {
    int i = blockIdx.x * blockDim.x + threadIdx.x;
    if (i >= 262144) return;
    float v;
    if (g_flags[1] == 0)        v = (float)((const int*)mp)[i];           // int32 0/1
    else if (g_flags[0] == 0)   v = ((const float*)mp)[i];                // float 0/1
    else                        v = (float)((const unsigned char*)mp)[i]; // bool bytes
    o[i] = v;
}

// ---------------- mask maxpool 3^3 stride 2 pad 1 ----------------
__global__ void k_downmask(const float* __restrict__ m, float* __restrict__ o, int Do) {
    int i = blockIdx.x * blockDim.x + threadIdx.x;
    int n = Do * Do * Do;
    if (i >= n) return;
    int Di = Do * 2;
    int x = i % Do, y = (i / Do) % Do, z = i / (Do * Do);
    float v = 0.f;
    for (int dz = -1; dz <= 1; dz++) {
        int iz = 2 * z + dz; if (iz < 0 || iz >= Di) continue;
        for (int dy = -1; dy <= 1; dy++) {
            int iy = 2 * y + dy; if (iy < 0 || iy >= Di) continue;
            for (int dx = -1; dx <= 1; dx++) {
                int ix = 2 * x + dx; if (ix < 0 || ix >= Di) continue;
                v = fmaxf(v, m[(iz * Di + iy) * Di + ix]);
            }
        }
    }
    o[i] = v;
}

// ---------------- BN fold: scale = g*rsqrt(v+eps), shift = b - mu*scale ----------------
__global__ void k_prep_bn(const float* __restrict__ bn, int C, int off) {
    int i = blockIdx.x * blockDim.x + threadIdx.x;
    if (i >= C) return;
    float g = bn[i], b = bn[C + i], mu = bn[2 * C + i], var = bn[3 * C + i];
    float s = g * rsqrtf(var + EPSBN);
    g_scale[off + i] = s;
    g_shift[off + i] = b - mu * s;
}

// ---------------- x * mask (broadcast over channels) ----------------
__global__ void k_mulmask(const float* __restrict__ x, const float* __restrict__ m,
                          float* __restrict__ o, int total, int Vmask) {
    int i = blockIdx.x * blockDim.x + threadIdx.x;
    if (i >= total) return;
    o[i] = x[i] * m[i & (Vmask - 1)];
}

// ---------------- fused conv3x3x3 stride1 + BN + ReLU + mask ----------------
// Block: 128 threads; output tile 8(x) x 4(y) x 8(z), 2 z-voxels per thread,
// 8 output channels per thread kept in registers.
__global__ __launch_bounds__(128) void k_conv_s1(
    const float* __restrict__ in, const float* __restrict__ w,
    const float* __restrict__ mask, float* __restrict__ out,
    int D, int Cin, int bnoff)
{
    __shared__ float s_in[600];      // 10(z) x 6(y) x 10(x)
    __shared__ float s_w[8][27];
    const int tid = threadIdx.x;
    const int lx = tid & 7, ly = (tid >> 3) & 3, lz = tid >> 5;   // lz in [0,4)
    const int ntY = D >> 2;
    const int bx = blockIdx.x, by = blockIdx.y % ntY, bz = blockIdx.y / ntY;
    const int oc0 = blockIdx.z * 8;
    const int x0 = bx * 8 - 1, y0 = by * 4 - 1, z0 = bz * 8 - 1;
    const int DD = D * D;

    float acc[16];
#pragma unroll
    for (int i = 0; i < 16; i++) acc[i] = 0.f;

    for (int ci = 0; ci < Cin; ci++) {
        const float* inc = in + (size_t)ci * D * DD;
        for (int i = tid; i < 600; i += 128) {
            int xx = i % 10; int t = i / 10; int yy = t % 6; int zz = t / 6;
            int gx = x0 + xx, gy = y0 + yy, gz = z0 + zz;
            float v = 0.f;
            if ((unsigned)gx < (unsigned)D && (unsigned)gy < (unsigned)D && (unsigned)gz < (unsigned)D)
                v = inc[gz * DD + gy * D + gx];
            s_in[i] = v;
        }
        {
            const float* wc = w + ((size_t)oc0 * Cin + ci) * 27;
            for (int i = tid; i < 216; i += 128) {
                int co = i / 27, k = i % 27;
                s_w[co][k] = wc[(size_t)co * Cin * 27 + k];
            }
        }
        __syncthreads();

        const float* b0 = &s_in[lz * 60 + ly * 10 + lx];
        float r0[27], r1[27];
#pragma unroll
        for (int dz = 0; dz < 3; dz++)
#pragma unroll
            for (int dy = 0; dy < 3; dy++)
#pragma unroll
                for (int dx = 0; dx < 3; dx++) {
                    r0[(dz * 3 + dy) * 3 + dx] = b0[dz * 60 + dy * 10 + dx];
                    r1[(dz * 3 + dy) * 3 + dx] = b0[(dz + 4) * 60 + dy * 10 + dx];
                }
#pragma unroll
        for (int co = 0; co < 8; co++) {
            float a0 = acc[co], a1 = acc[8 + co];
#pragma unroll
            for (int k = 0; k < 27; k++) {
                float wv = s_w[co][k];
                a0 = fmaf(r0[k], wv, a0);
                a1 = fmaf(r1[k], wv, a1);
            }
            acc[co] = a0; acc[8 + co] = a1;
        }
        __syncthreads();
    }

    const int ox = bx * 8 + lx, oy = by * 4 + ly;
    const int ozA = bz * 8 + lz, ozB = ozA + 4;
    const float mA = mask[ozA * DD + oy * D + ox];
    const float mB = mask[ozB * DD + oy * D + ox];
#pragma unroll
    for (int co = 0; co < 8; co++) {
        int c = oc0 + co;
        float s = g_scale[bnoff + c], sh = g_shift[bnoff + c];
        float vA = fmaxf(fmaf(acc[co],     s, sh), 0.f) * mA;
        float vB = fmaxf(fmaf(acc[8 + co], s, sh), 0.f) * mB;
        out[(size_t)c * D * DD + ozA * DD + oy * D + ox] = vA;
        out[(size_t)c * D * DD + ozB * DD + oy * D + ox] = vB;
    }
}

// ---------------- fused conv3x3x3 stride2 + BN + ReLU + mask(downsampled) ----------------
// Block: 64 threads; output tile 4x4x4, 8 output channels per thread.
__global__ __launch_bounds__(64) void k_conv_s2(
    const float* __restrict__ in, const float* __restrict__ w,
    const float* __restrict__ mask, float* __restrict__ out,
    int Do, int Cin, int bnoff)
{
    __shared__ float s_in[729];      // 9 x 9 x 9
    __shared__ float s_w[8][27];
    const int Di = Do * 2;
    const int tid = threadIdx.x;
    const int lx = tid & 3, ly = (tid >> 2) & 3, lz = tid >> 4;
    const int ntY = Do >> 2;
    const int bx = blockIdx.x, by = blockIdx.y % ntY, bz = blockIdx.y / ntY;
    const int oc0 = blockIdx.z * 8;
    const int x0 = bx * 8 - 1, y0 = by * 8 - 1, z0 = bz * 8 - 1;
    const int DiDi = Di * Di;

    float acc[8];
#pragma unroll
    for (int i = 0; i < 8; i++) acc[i] = 0.f;

    for (int ci = 0; ci < Cin; ci++) {
        const float* inc = in + (size_t)ci * Di * DiDi;
        for (int i = tid; i < 729; i += 64) {
            int xx = i % 9; int t = i / 9; int yy = t % 9; int zz = t / 9;
            int gx = x0 + xx, gy = y0 + yy, gz = z0 + zz;
            float v = 0.f;
            if ((unsigned)gx < (unsigned)Di && (unsigned)gy < (unsigned)Di && (unsigned)gz < (unsigned)Di)
                v = inc[gz * DiDi + gy * Di + gx];
            s_in[i] = v;
        }
        {
            const float* wc = w + ((size_t)oc0 * Cin + ci) * 27;
            for (int i = tid; i < 216; i += 64) {
                int co = i / 27, k = i % 27;
                s_w[co][k] = wc[(size_t)co * Cin * 27 + k];
            }
        }
        __syncthreads();

        const float* b0 = &s_in[(2 * lz) * 81 + (2 * ly) * 9 + 2 * lx];
        float r[27];
#pragma unroll
        for (int dz = 0; dz < 3; dz++)
#pragma unroll
            for (int dy = 0; dy < 3; dy++)
#pragma unroll
                for (int dx = 0; dx < 3; dx++)
                    r[(dz * 3 + dy) * 3 + dx] = b0[dz * 81 + dy * 9 + dx];
#pragma unroll
        for (int co = 0; co < 8; co++) {
            float a = acc[co];
#pragma unroll
            for (int k = 0; k < 27; k++)
                a = fmaf(r[k], s_w[co][k], a);
            acc[co] = a;
        }
        __syncthreads();
    }

    const int ox = bx * 4 + lx, oy = by * 4 + ly, oz = bz * 4 + lz;
    const int DoDo = Do * Do;
    const float mv = mask[oz * DoDo + oy * Do + ox];
#pragma unroll
    for (int co = 0; co < 8; co++) {
        int c = oc0 + co;
        float s = g_scale[bnoff + c], sh = g_shift[bnoff + c];
        float v = fmaxf(fmaf(acc[co], s, sh), 0.f) * mv;
        out[(size_t)c * Do * DoDo + oz * DoDo + oy * Do + ox] = v;
    }
}

// ---------------- triplane mean pooling (writes channel-fastest planes) ----------------
// x: (128, 16, 16, 16) channel-major.  planes: [(a*16+b)*128 + c]
__global__ void k_pool(const float* __restrict__ x) {
    int i = blockIdx.x * blockDim.x + threadIdx.x;      // 32768
    if (i >= 32768) return;
    int c = i % 128; int ab = i / 128; int a = ab / 16, b = ab % 16;
    const float inv = 1.f / 16.f;
    float s;
    // p_xy: mean over D(axis2). a = h, b = w.
    s = 0.f;
    for (int d = 0; d < 16; d++) s += x[((c * 16 + d) * 16 + a) * 16 + b];
    g_pxy[(a * 16 + b) * 128 + c] = s * inv;
    // p_yz: mean over W(axis4). a = d, b = h.
    s = 0.f;
    for (int w_ = 0; w_ < 16; w_++) s += x[((c * 16 + a) * 16 + b) * 16 + w_];
    g_pyz[(a * 16 + b) * 128 + c] = s * inv;
    // p_xz: mean over H(axis3). a = d, b = w.
    s = 0.f;
    for (int h = 0; h < 16; h++) s += x[((c * 16 + a) * 16 + h) * 16 + b];
    g_pxz[(a * 16 + b) * 128 + c] = s * inv;
}

// ---------------- grid sample (bilinear, border-valid like reference) ----------------
__device__ __forceinline__ float bilin(const float* __restrict__ img, float gx, float gy, int c) {
    float ix = (gx + 1.f) * 0.5f * 15.f;
    float iy = (gy + 1.f) * 0.5f * 15.f;
    float x0f = floorf(ix), y0f = floorf(iy);
    float wx = ix - x0f, wy = iy - y0f;
    int x0 = (int)x0f, y0 = (int)y0f;
    float r = 0.f;
#pragma unroll
    for (int j = 0; j < 2; j++) {
        int yy = y0 + j;
        float wyj = j ? wy : 1.f - wy;
        if (yy < 0 || yy > 15) continue;
#pragma unroll
        for (int i2 = 0; i2 < 2; i2++) {
            int xx = x0 + i2;
            float wxi = i2 ? wx : 1.f - wx;
            if (xx < 0 || xx > 15) continue;
            r += img[(yy * 16 + xx) * 128 + c] * (wyj * wxi);
        }
    }
    return r;
}

__global__ void k_gridsample(const float* __restrict__ coords, float* __restrict__ out) {
    int p = blockIdx.x;
    int c = threadIdx.x;
    float c0 = coords[p * 3 + 0], c1 = coords[p * 3 + 1], c2 = coords[p * 3 + 2];
    float f = bilin(g_pxy, c0, c1, c)
            + bilin(g_pyz, c1, c2, c)
            + bilin(g_pxz, c0, c2, c);
    out[(size_t)p * 128 + c] = f;
}

// ---------------- host launch ----------------
extern "C" void kernel_launch(void* const* d_in, const int* in_sizes, int n_in,
                              void* d_out, int out_size) {
    const float* x      = (const float*)d_in[0];
    const void*  maskp  = d_in[1];
    const float* coords = (const float*)d_in[2];
    const float* w0a = (const float*)d_in[3];  const float* bn0a = (const float*)d_in[4];
    const float* w0b = (const float*)d_in[5];  const float* bn0b = (const float*)d_in[6];
    const float* wd0 = (const float*)d_in[7];  const float* bnd0 = (const float*)d_in[8];
    const float* w1a = (const float*)d_in[9];  const float* bn1a = (const float*)d_in[10];
    const float* w1b = (const float*)d_in[11]; const float* bn1b = (const float*)d_in[12];
    const float* wd1 = (const float*)d_in[13]; const float* bnd1 = (const float*)d_in[14];
    const float* w2a = (const float*)d_in[15]; const float* bn2a = (const float*)d_in[16];
    const float* w2b = (const float*)d_in[17]; const float* bn2b = (const float*)d_in[18];
    const float* w2c = (const float*)d_in[19]; const float* bn2c = (const float*)d_in[20];

    float *bufA, *bufB, *m0, *m1, *m2;
    cudaGetSymbolAddress((void**)&bufA, g_bufA);
    cudaGetSymbolAddress((void**)&bufB, g_bufB);
    cudaGetSymbolAddress((void**)&m0, g_m0);
    cudaGetSymbolAddress((void**)&m1, g_m1);
    cudaGetSymbolAddress((void**)&m2, g_m2);

    // mask prep (dtype-robust)
    k_init_flags<<<1, 32>>>();
    k_detect<<<256, 256>>>((const unsigned int*)maskp);
    k_expand_mask<<<1024, 256>>>(maskp, m0);
    k_downmask<<<(32768 + 255) / 256, 256>>>(m0, m1, 32);
    k_downmask<<<(4096 + 255) / 256, 256>>>(m1, m2, 16);

    // BN folds: offsets in g_scale/g_shift
    k_prep_bn<<<1, 32>>>(bn0a, 32, 0);
    k_prep_bn<<<1, 32>>>(bn0b, 32, 32);
    k_prep_bn<<<1, 32>>>(bnd0, 32, 64);
    k_prep_bn<<<1, 64>>>(bn1a, 64, 96);
    k_prep_bn<<<1, 64>>>(bn1b, 64, 160);
    k_prep_bn<<<1, 128>>>(bnd1, 128, 224);
    k_prep_bn<<<1, 128>>>(bn2a, 128, 352);
    k_prep_bn<<<1, 128>>>(bn2b, 128, 480);
    k_prep_bn<<<1, 128>>>(bn2c, 128, 608);

    // x * mask
    k_mulmask<<<(16 * 262144 + 255) / 256, 256>>>(x, m0, bufA, 16 * 262144, 262144);

    // stage 0 @ 64^3
    k_conv_s1<<<dim3(8, 128, 4),  128>>>(bufA, w0a, m0, bufB, 64, 16, 0);
    k_conv_s1<<<dim3(8, 128, 4),  128>>>(bufB, w0b, m0, bufA, 64, 32, 32);
    k_conv_s2<<<dim3(8, 64, 4),    64>>>(bufA, wd0, m1, bufB, 32, 32, 64);
    // stage 1 @ 32^3
    k_conv_s1<<<dim3(4, 32, 8),   128>>>(bufB, w1a, m1, bufA, 32, 32, 96);
    k_conv_s1<<<dim3(4, 32, 8),   128>>>(bufA, w1b, m1, bufB, 32, 64, 160);
    k_conv_s2<<<dim3(4, 16, 16),   64>>>(bufB, wd1, m2, bufA, 16, 64, 224);
    // stage 2 @ 16^3
    k_conv_s1<<<dim3(2, 8, 16),   128>>>(bufA, w2a, m2, bufB, 16, 128, 352);
    k_conv_s1<<<dim3(2, 8, 16),   128>>>(bufB, w2b, m2, bufA, 16, 128, 480);
    k_conv_s1<<<dim3(2, 8, 16),   128>>>(bufA, w2c, m2, bufB, 16, 128, 608);

    // triplane pooling + grid sample
    k_pool<<<128, 256>>>(bufB);
    k_gridsample<<<65536, 128>>>(coords, (float*)d_out);
}

// round 7
// speedup vs baseline: 1.6976x; 1.6976x over previous
#include <cuda_runtime.h>
#include <cstdint>

#define EPSBN 0.001f

// ---------------- static device scratch ----------------
__device__ float g_bufA[32u * 262144u];
__device__ float g_bufB[32u * 262144u];
__device__ float g_m0[262144];
__device__ float g_m1[32768];
__device__ float g_m2[4096];
__device__ float g_pxy[32768];   // [(a*16+b)*128 + c]
__device__ float g_pyz[32768];
__device__ float g_pxz[32768];
__device__ int   g_flags[2];

// ---------------- mask dtype detection + expansion ----------------
__global__ void k_init_flags() { if (threadIdx.x < 2) g_flags[threadIdx.x] = 0; }

__global__ void k_detect(const unsigned int* __restrict__ m) {
    int i = blockIdx.x * blockDim.x + threadIdx.x;
    if (i < 65536) {
        unsigned v = m[i];
        if (v != 0u && v != 0x3F800000u) atomicOr(&g_flags[0], 1);
        if (v > 1u) atomicOr(&g_flags[1], 1);
    }
}

__global__ void k_expand_mask(const void* __restrict__ mp, float* __restrict__ o) {
    int i = blockIdx.x * blockDim.x + threadIdx.x;
    if (i >= 262144) return;
    float v;
    if (g_flags[1] == 0)      v = (float)((const int*)mp)[i];
    else if (g_flags[0] == 0) v = ((const float*)mp)[i];
    else                      v = (float)((const unsigned char*)mp)[i];
    o[i] = v;
}

// ---------------- mask maxpool 3^3 s2 p1 ----------------
__global__ void k_downmask(const float* __restrict__ m, float* __restrict__ o, int Do) {
    int i = blockIdx.x * blockDim.x + threadIdx.x;
    int n = Do * Do * Do;
    if (i >= n) return;
    int Di = Do * 2;
    int x = i % Do, y = (i / Do) % Do, z = i / (Do * Do);
    float v = 0.f;
    for (int dz = -1; dz <= 1; dz++) {
        int iz = 2 * z + dz; if (iz < 0 || iz >= Di) continue;
        for (int dy = -1; dy <= 1; dy++) {
            int iy = 2 * y + dy; if (iy < 0 || iy >= Di) continue;
            for (int dx = -1; dx <= 1; dx++) {
                int ix = 2 * x + dx; if (ix < 0 || ix >= Di) continue;
                v = fmaxf(v, m[(iz * Di + iy) * Di + ix]);
            }
        }
    }
    o[i] = v;
}

// ============ fused conv3x3x3 s1 + BN + ReLU + mask ============
// 128 threads; out tile 8(x) x 4(y) x (4*VZ)(z); COUT channels/block.
// Double-buffered smem, float4 weight broadcasts, BN folded in epilogue.
template<int COUT, int VZ, bool PREMASK>
__global__ __launch_bounds__(128) void k_conv_s1(
    const float* __restrict__ in, const float* __restrict__ w,
    const float* __restrict__ bn,
    const float* __restrict__ inmask, const float* __restrict__ outmask,
    float* __restrict__ out, int D, int Cin, int Ctot)
{
    constexpr int ZT  = 4 * VZ;
    constexpr int TIN = (ZT + 2) * 6 * 10;
    constexpr int NW  = 27 * COUT;
    constexpr int LDI = (TIN + 127) / 128;
    constexpr int LDW = (NW + 127) / 128;
    __shared__ float s_in[2][TIN];
    __shared__ __align__(16) float s_w[2][NW];

    const int tid = threadIdx.x;
    const int lx = tid & 7, ly = (tid >> 3) & 3, lz = tid >> 5;
    const int ntY = D >> 2;
    const int bx = blockIdx.x, by = blockIdx.y % ntY, bz = blockIdx.y / ntY;
    const int oc0 = blockIdx.z * COUT;
    const int x0 = bx * 8 - 1, y0 = by * 4 - 1, z0 = bz * ZT - 1;
    const int DD = D * D;

    // precomputed input tile offsets (constant across cin)
    int ioff[LDI]; bool iok[LDI]; float mval[LDI];
#pragma unroll
    for (int j = 0; j < LDI; j++) {
        int i = tid + 128 * j;
        int xx = i % 10, t = i / 10, yy = t % 6, zz = t / 6;
        int gx = x0 + xx, gy = y0 + yy, gz = z0 + zz;
        bool ok = (i < TIN) && (unsigned)gx < (unsigned)D &&
                  (unsigned)gy < (unsigned)D && (unsigned)gz < (unsigned)D;
        iok[j] = ok;
        ioff[j] = ok ? gz * DD + gy * D + gx : 0;
        if (PREMASK) mval[j] = ok ? inmask[ioff[j]] : 0.f;
    }
    // precomputed weight offsets: smem layout [k][co]
    int woff[LDW]; int wsm[LDW];
#pragma unroll
    for (int j = 0; j < LDW; j++) {
        int i = tid + 128 * j;
        if (i < NW) { int co = i / 27, k = i % 27; woff[j] = (oc0 + co) * Cin * 27 + k; wsm[j] = k * COUT + co; }
        else        { woff[j] = -1; wsm[j] = 0; }
    }

    auto loadci = [&](int ci, int b) {
        const float* inc = in + (size_t)ci * D * DD;
#pragma unroll
        for (int j = 0; j < LDI; j++) {
            int i = tid + 128 * j;
            if (i < TIN) {
                float v = iok[j] ? inc[ioff[j]] : 0.f;
                if (PREMASK) v *= mval[j];
                s_in[b][i] = v;
            }
        }
        const float* wc = w + ci * 27;
#pragma unroll
        for (int j = 0; j < LDW; j++)
            if (woff[j] >= 0) s_w[b][wsm[j]] = wc[woff[j]];
    };

    float acc[VZ * COUT];
#pragma unroll
    for (int i = 0; i < VZ * COUT; i++) acc[i] = 0.f;

    loadci(0, 0);
    int b = 0;
    for (int ci = 0; ci < Cin; ci++) {
        __syncthreads();
        if (ci + 1 < Cin) loadci(ci + 1, b ^ 1);
        const float* base = &s_in[b][lz * 60 + ly * 10 + lx];
        const float4* wv = (const float4*)(s_w[b]);
#pragma unroll
        for (int dz = 0; dz < 3; dz++)
#pragma unroll
            for (int dy = 0; dy < 3; dy++)
#pragma unroll
                for (int dx = 0; dx < 3; dx++) {
                    const int k = (dz * 3 + dy) * 3 + dx;
                    float v[VZ];
#pragma unroll
                    for (int vv = 0; vv < VZ; vv++)
                        v[vv] = base[(4 * vv + dz) * 60 + dy * 10 + dx];
#pragma unroll
                    for (int q = 0; q < COUT / 4; q++) {
                        float4 ww = wv[k * (COUT / 4) + q];
#pragma unroll
                        for (int vv = 0; vv < VZ; vv++) {
                            acc[vv * COUT + 4 * q + 0] = fmaf(v[vv], ww.x, acc[vv * COUT + 4 * q + 0]);
                            acc[vv * COUT + 4 * q + 1] = fmaf(v[vv], ww.y, acc[vv * COUT + 4 * q + 1]);
                            acc[vv * COUT + 4 * q + 2] = fmaf(v[vv], ww.z, acc[vv * COUT + 4 * q + 2]);
                            acc[vv * COUT + 4 * q + 3] = fmaf(v[vv], ww.w, acc[vv * COUT + 4 * q + 3]);
                        }
                    }
                }
        b ^= 1;
    }

    const int ox = bx * 8 + lx, oy = by * 4 + ly;
#pragma unroll
    for (int vv = 0; vv < VZ; vv++) {
        int oz = bz * ZT + lz + 4 * vv;
        float mv = outmask[oz * DD + oy * D + ox];
#pragma unroll
        for (int co = 0; co < COUT; co++) {
            int c = oc0 + co;
            float g = bn[c], bb = bn[Ctot + c], mu = bn[2 * Ctot + c], vr = bn[3 * Ctot + c];
            float s = g * rsqrtf(vr + EPSBN);
            float sh = bb - mu * s;
            out[(size_t)c * D * DD + oz * DD + oy * D + ox] =
                fmaxf(fmaf(acc[vv * COUT + co], s, sh), 0.f) * mv;
        }
    }
}

// ============ fused conv3x3x3 s2 + BN + ReLU + mask ============
// 64 threads; out tile 4x4x4; COUT=16 channels/block; double-buffered.
template<int COUT>
__global__ __launch_bounds__(64) void k_conv_s2(
    const float* __restrict__ in, const float* __restrict__ w,
    const float* __restrict__ bn,
    const float* __restrict__ mask, float* __restrict__ out,
    int Do, int Cin, int Ctot)
{
    constexpr int TIN = 729;
    constexpr int NW  = 27 * COUT;
    constexpr int LDI = (TIN + 63) / 64;
    constexpr int LDW = (NW + 63) / 64;
    __shared__ float s_in[2][TIN];
    __shared__ __align__(16) float s_w[2][NW];

    const int Di = Do * 2;
    const int tid = threadIdx.x;
    const int lx = tid & 3, ly = (tid >> 2) & 3, lz = tid >> 4;
    const int ntY = Do >> 2;
    const int bx = blockIdx.x, by = blockIdx.y % ntY, bz = blockIdx.y / ntY;
    const int oc0 = blockIdx.z * COUT;
    const int x0 = bx * 8 - 1, y0 = by * 8 - 1, z0 = bz * 8 - 1;
    const int DiDi = Di * Di;

    int ioff[LDI]; bool iok[LDI];
#pragma unroll
    for (int j = 0; j < LDI; j++) {
        int i = tid + 64 * j;
        int xx = i % 9, t = i / 9, yy = t % 9, zz = t / 9;
        int gx = x0 + xx, gy = y0 + yy, gz = z0 + zz;
        bool ok = (i < TIN) && (unsigned)gx < (unsigned)Di &&
                  (unsigned)gy < (unsigned)Di && (unsigned)gz < (unsigned)Di;
        iok[j] = ok;
        ioff[j] = ok ? gz * DiDi + gy * Di + gx : 0;
    }
    int woff[LDW]; int wsm[LDW];
#pragma unroll
    for (int j = 0; j < LDW; j++) {
        int i = tid + 64 * j;
        if (i < NW) { int co = i / 27, k = i % 27; woff[j] = (oc0 + co) * Cin * 27 + k; wsm[j] = k * COUT + co; }
        else        { woff[j] = -1; wsm[j] = 0; }
    }

    auto loadci = [&](int ci, int b) {
        const float* inc = in + (size_t)ci * Di * DiDi;
#pragma unroll
        for (int j = 0; j < LDI; j++) {
            int i = tid + 64 * j;
            if (i < TIN) s_in[b][i] = iok[j] ? inc[ioff[j]] : 0.f;
        }
        const float* wc = w + ci * 27;
#pragma unroll
        for (int j = 0; j < LDW; j++)
            if (woff[j] >= 0) s_w[b][wsm[j]] = wc[woff[j]];
    };

    float acc[COUT];
#pragma unroll
    for (int i = 0; i < COUT; i++) acc[i] = 0.f;

    loadci(0, 0);
    int b = 0;
    for (int ci = 0; ci < Cin; ci++) {
        __syncthreads();
        if (ci + 1 < Cin) loadci(ci + 1, b ^ 1);
        const float* base = &s_in[b][(2 * lz) * 81 + (2 * ly) * 9 + 2 * lx];
        const float4* wv = (const float4*)(s_w[b]);
#pragma unroll
        for (int dz = 0; dz < 3; dz++)
#pragma unroll
            for (int dy = 0; dy < 3; dy++)
#pragma unroll
                for (int dx = 0; dx < 3; dx++) {
                    const int k = (dz * 3 + dy) * 3 + dx;
                    float v = base[dz * 81 + dy * 9 + dx];
#pragma unroll
                    for (int q = 0; q < COUT / 4; q++) {
                        float4 ww = wv[k * (COUT / 4) + q];
                        acc[4 * q + 0] = fmaf(v, ww.x, acc[4 * q + 0]);
                        acc[4 * q + 1] = fmaf(v, ww.y, acc[4 * q + 1]);
                        acc[4 * q + 2] = fmaf(v, ww.z, acc[4 * q + 2]);
                        acc[4 * q + 3] = fmaf(v, ww.w, acc[4 * q + 3]);
                    }
                }
        b ^= 1;
    }

    const int ox = bx * 4 + lx, oy = by * 4 + ly, oz = bz * 4 + lz;
    const int DoDo = Do * Do;
    const float mv = mask[oz * DoDo + oy * Do + ox];
#pragma unroll
    for (int co = 0; co < COUT; co++) {
        int c = oc0 + co;
        float g = bn[c], bb = bn[Ctot + c], mu = bn[2 * Ctot + c], vr = bn[3 * Ctot + c];
        float s = g * rsqrtf(vr + EPSBN);
        float sh = bb - mu * s;
        out[(size_t)c * Do * DoDo + oz * DoDo + oy * Do + ox] =
            fmaxf(fmaf(acc[co], s, sh), 0.f) * mv;
    }
}

// ---------------- triplane mean pooling ----------------
__global__ void k_pool(const float* __restrict__ x) {
    int i = blockIdx.x * blockDim.x + threadIdx.x;
    if (i >= 32768) return;
    int c = i % 128; int ab = i / 128; int a = ab / 16, b = ab % 16;
    const float inv = 1.f / 16.f;
    float s;
    s = 0.f;
    for (int d = 0; d < 16; d++) s += x[((c * 16 + d) * 16 + a) * 16 + b];
    g_pxy[(a * 16 + b) * 128 + c] = s * inv;
    s = 0.f;
    for (int w_ = 0; w_ < 16; w_++) s += x[((c * 16 + a) * 16 + b) * 16 + w_];
    g_pyz[(a * 16 + b) * 128 + c] = s * inv;
    s = 0.f;
    for (int h = 0; h < 16; h++) s += x[((c * 16 + a) * 16 + h) * 16 + b];
    g_pxz[(a * 16 + b) * 128 + c] = s * inv;
}

// ---------------- grid sample ----------------
__device__ __forceinline__ float bilin(const float* __restrict__ img, float gx, float gy, int c) {
    float ix = (gx + 1.f) * 0.5f * 15.f;
    float iy = (gy + 1.f) * 0.5f * 15.f;
    float x0f = floorf(ix), y0f = floorf(iy);
    float wx = ix - x0f, wy = iy - y0f;
    int x0 = (int)x0f, y0 = (int)y0f;
    float r = 0.f;
#pragma unroll
    for (int j = 0; j < 2; j++) {
        int yy = y0 + j;
        float wyj = j ? wy : 1.f - wy;
        if (yy < 0 || yy > 15) continue;
#pragma unroll
        for (int i2 = 0; i2 < 2; i2++) {
            int xx = x0 + i2;
            float wxi = i2 ? wx : 1.f - wx;
            if (xx < 0 || xx > 15) continue;
            r += img[(yy * 16 + xx) * 128 + c] * (wyj * wxi);
        }
    }
    return r;
}

__global__ void k_gridsample(const float* __restrict__ coords, float* __restrict__ out) {
    int p = blockIdx.x;
    int c = threadIdx.x;
    float c0 = coords[p * 3 + 0], c1 = coords[p * 3 + 1], c2 = coords[p * 3 + 2];
    float f = bilin(g_pxy, c0, c1, c)
            + bilin(g_pyz, c1, c2, c)
            + bilin(g_pxz, c0, c2, c);
    out[(size_t)p * 128 + c] = f;
}

// ---------------- host launch ----------------
extern "C" void kernel_launch(void* const* d_in, const int* in_sizes, int n_in,
                              void* d_out, int out_size) {
    const float* x      = (const float*)d_in[0];
    const void*  maskp  = d_in[1];
    const float* coords = (const float*)d_in[2];
    const float* w0a = (const float*)d_in[3];  const float* bn0a = (const float*)d_in[4];
    const float* w0b = (const float*)d_in[5];  const float* bn0b = (const float*)d_in[6];
    const float* wd0 = (const float*)d_in[7];  const float* bnd0 = (const float*)d_in[8];
    const float* w1a = (const float*)d_in[9];  const float* bn1a = (const float*)d_in[10];
    const float* w1b = (const float*)d_in[11]; const float* bn1b = (const float*)d_in[12];
    const float* wd1 = (const float*)d_in[13]; const float* bnd1 = (const float*)d_in[14];
    const float* w2a = (const float*)d_in[15]; const float* bn2a = (const float*)d_in[16];
    const float* w2b = (const float*)d_in[17]; const float* bn2b = (const float*)d_in[18];
    const float* w2c = (const float*)d_in[19]; const float* bn2c = (const float*)d_in[20];

    float *bufA, *bufB, *m0, *m1, *m2;
    cudaGetSymbolAddress((void**)&bufA, g_bufA);
    cudaGetSymbolAddress((void**)&bufB, g_bufB);
    cudaGetSymbolAddress((void**)&m0, g_m0);
    cudaGetSymbolAddress((void**)&m1, g_m1);
    cudaGetSymbolAddress((void**)&m2, g_m2);

    // mask prep (launches 0-4) -> conv0a is launch 5 (ncu -s 5 -c 1 profiles it)
    k_init_flags<<<1, 32>>>();
    k_detect<<<256, 256>>>((const unsigned int*)maskp);
    k_expand_mask<<<1024, 256>>>(maskp, m0);
    k_downmask<<<(32768 + 255) / 256, 256>>>(m0, m1, 32);
    k_downmask<<<(4096 + 255) / 256, 256>>>(m1, m2, 16);

    // stage 0 @ 64^3  (x*mask fused into conv0a tile load)
    k_conv_s1<16, 2, true ><<<dim3(8, 128, 2), 128>>>(x,    w0a, bn0a, m0, m0, bufA, 64, 16, 32);
    k_conv_s1<16, 2, false><<<dim3(8, 128, 2), 128>>>(bufA, w0b, bn0b, nullptr, m0, bufB, 64, 32, 32);
    k_conv_s2<16><<<dim3(8, 64, 2), 64>>>(bufB, wd0, bnd0, m1, bufA, 32, 32, 32);
    // stage 1 @ 32^3
    k_conv_s1<16, 2, false><<<dim3(4, 32, 4), 128>>>(bufA, w1a, bn1a, nullptr, m1, bufB, 32, 32, 64);
    k_conv_s1<16, 2, false><<<dim3(4, 32, 4), 128>>>(bufB, w1b, bn1b, nullptr, m1, bufA, 32, 64, 64);
    k_conv_s2<16><<<dim3(4, 16, 8), 64>>>(bufA, wd1, bnd1, m2, bufB, 16, 64, 128);
    // stage 2 @ 16^3  (VZ=1 -> 256 blocks for occupancy)
    k_conv_s1<16, 1, false><<<dim3(2, 16, 8), 128>>>(bufB, w2a, bn2a, nullptr, m2, bufA, 16, 128, 128);
    k_conv_s1<16, 1, false><<<dim3(2, 16, 8), 128>>>(bufA, w2b, bn2b, nullptr, m2, bufB, 16, 128, 128);
    k_conv_s1<16, 1, false><<<dim3(2, 16, 8), 128>>>(bufB, w2c, bn2c, nullptr, m2, bufA, 16, 128, 128);

    // triplane pooling + grid sample
    k_pool<<<128, 256>>>(bufA);
    k_gridsample<<<65536, 128>>>(coords, (float*)d_out);
}